// round 2
// baseline (speedup 1.0000x reference)
#include <cuda_runtime.h>
#include <math.h>

#define BATCH 8
#define T 2048
#define C 1024
#define H 64

// Scratch for projected k and v: [B, T, H] fp32, 4 MB each.
__device__ float g_k[BATCH * T * H];
__device__ float g_v[BATCH * T * H];

// ---------------------------------------------------------------------------
// Projection: kv[m, n] = sum_k x[m, k] * W[n, k],  W = concat(W_k, W_v) (N=128)
// Tiles: BM=128, BN=128, BK=16. 256 threads, 8x8 microtile per thread.
// Microtile cols split: {tn*4 .. +3} -> k outputs, {64 + tn*4 .. +3} -> v outputs.
// ---------------------------------------------------------------------------
#define PBM 128
#define PBN 128
#define PBK 16

__global__ void __launch_bounds__(256) proj_kernel(const float* __restrict__ x,
                                                   const float* __restrict__ Wk,
                                                   const float* __restrict__ Wv) {
    __shared__ float As[PBK][PBM + 4];  // transposed: As[k][m]
    __shared__ float Bs[PBK][PBN + 4];  // transposed: Bs[k][n]

    const int tid = threadIdx.x;
    const int m0 = blockIdx.x * PBM;
    const int tm = tid >> 4;   // 0..15 -> rows tm*8 .. tm*8+7
    const int tn = tid & 15;   // 0..15 -> cols tn*4 (k) and 64+tn*4 (v)

    float acc[8][8];
#pragma unroll
    for (int i = 0; i < 8; i++)
#pragma unroll
        for (int j = 0; j < 8; j++) acc[i][j] = 0.f;

    for (int k0 = 0; k0 < C; k0 += PBK) {
        // Load X tile (128 x 16) -> As[k][m]
#pragma unroll
        for (int l = 0; l < 2; l++) {
            int t = tid + l * 256;         // 0..511
            int m = t >> 2;                // 0..127
            int kc = (t & 3) * 4;          // 0,4,8,12
            float4 v = *reinterpret_cast<const float4*>(x + (size_t)(m0 + m) * C + k0 + kc);
            As[kc + 0][m] = v.x; As[kc + 1][m] = v.y;
            As[kc + 2][m] = v.z; As[kc + 3][m] = v.w;
        }
        // Load W tile (128 x 16) -> Bs[k][n]; n<64 from Wk, else Wv
#pragma unroll
        for (int l = 0; l < 2; l++) {
            int t = tid + l * 256;
            int n = t >> 2;
            int kc = (t & 3) * 4;
            const float* wsrc = (n < 64) ? (Wk + (size_t)n * C) : (Wv + (size_t)(n - 64) * C);
            float4 v = *reinterpret_cast<const float4*>(wsrc + k0 + kc);
            Bs[kc + 0][n] = v.x; Bs[kc + 1][n] = v.y;
            Bs[kc + 2][n] = v.z; Bs[kc + 3][n] = v.w;
        }
        __syncthreads();

#pragma unroll
        for (int k = 0; k < PBK; k++) {
            float a[8], b[8];
            *reinterpret_cast<float4*>(a)     = *reinterpret_cast<const float4*>(&As[k][tm * 8]);
            *reinterpret_cast<float4*>(a + 4) = *reinterpret_cast<const float4*>(&As[k][tm * 8 + 4]);
            *reinterpret_cast<float4*>(b)     = *reinterpret_cast<const float4*>(&Bs[k][tn * 4]);
            *reinterpret_cast<float4*>(b + 4) = *reinterpret_cast<const float4*>(&Bs[k][64 + tn * 4]);
#pragma unroll
            for (int i = 0; i < 8; i++)
#pragma unroll
                for (int j = 0; j < 8; j++)
                    acc[i][j] += a[i] * b[j];
        }
        __syncthreads();
    }

    // Write out: cols 0..3 -> g_k, cols 4..7 -> g_v
#pragma unroll
    for (int i = 0; i < 8; i++) {
        int m = m0 + tm * 8 + i;
        float* dk = g_k + (size_t)m * H + tn * 4;
        float* dv = g_v + (size_t)m * H + tn * 4;
        *reinterpret_cast<float4*>(dk) = make_float4(acc[i][0], acc[i][1], acc[i][2], acc[i][3]);
        *reinterpret_cast<float4*>(dv) = make_float4(acc[i][4], acc[i][5], acc[i][6], acc[i][7]);
    }
}

// ---------------------------------------------------------------------------
// Flash attention (q = k per reference). BQ=64 query rows per block, BK=64 key
// cols per iteration, 256 threads, 4x4 microtiles. Online softmax.
// ---------------------------------------------------------------------------
#define BQ 64
#define BKT 64
#define QSTR (BQ + 4)    // 68 (row stride for [h][r] / [j][r] arrays)
#define HSTR (H + 4)     // 68 (row stride for [j][c] array)
#define ATTN_SMEM (4 * 64 * 68 * 4)  // Qt + Kt + Vs + Pt = 69632 bytes

__global__ void __launch_bounds__(256, 2) attn_kernel(float* __restrict__ out) {
    extern __shared__ float smem[];
    float* Qt = smem;                 // [H][QSTR]   Qt[h*QSTR + r]
    float* Kt = Qt + 64 * QSTR;       // [H][QSTR]   Kt[h*QSTR + j]
    float* Vs = Kt + 64 * QSTR;       // [BKT][HSTR] Vs[j*HSTR + c]
    float* Pt = Vs + 64 * HSTR;       // [BKT][QSTR] Pt[j*QSTR + r]

    const int tid = threadIdx.x;
    const int b = blockIdx.y;
    // Reverse order: heaviest q-tiles (most kv iterations) launch first.
    const int qt = (int)gridDim.x - 1 - (int)blockIdx.x;
    const int q0 = qt * BQ;
    const int tm = tid >> 4;          // row group: rows r0..r0+3
    const int tn = tid & 15;          // col group: cols c0..c0+3
    const int r0 = tm * 4;
    const int c0 = tn * 4;

    const float* kb = g_k + (size_t)b * T * H;
    const float* vb = g_v + (size_t)b * T * H;

    // Load Q tile (rows q0..q0+63 of k projection) transposed into Qt[h][r]
#pragma unroll
    for (int l = 0; l < 4; l++) {
        int t = tid + l * 256;        // 0..1023
        int r = t >> 4;               // 0..63
        int hc = (t & 15) * 4;        // 0..60
        float4 q4 = *reinterpret_cast<const float4*>(kb + (size_t)(q0 + r) * H + hc);
        Qt[(hc + 0) * QSTR + r] = q4.x; Qt[(hc + 1) * QSTR + r] = q4.y;
        Qt[(hc + 2) * QSTR + r] = q4.z; Qt[(hc + 3) * QSTR + r] = q4.w;
    }

    float m_i[4], l_i[4], o[4][4];
#pragma unroll
    for (int i = 0; i < 4; i++) {
        m_i[i] = -INFINITY;
        l_i[i] = 0.f;
#pragma unroll
        for (int c = 0; c < 4; c++) o[i][c] = 0.f;
    }

    const float SCALE = 0.125f;  // 64^-0.5
    const int nkv = qt + 1;

    for (int kt2 = 0; kt2 < nkv; kt2++) {
        const int j0g = kt2 * BKT;
        __syncthreads();  // protect Kt/Vs/Pt from previous iteration readers

        // Load K tile transposed into Kt[h][j]; V tile direct into Vs[j][c]
#pragma unroll
        for (int l = 0; l < 4; l++) {
            int t = tid + l * 256;
            int j = t >> 4;
            int hc = (t & 15) * 4;
            float4 k4 = *reinterpret_cast<const float4*>(kb + (size_t)(j0g + j) * H + hc);
            Kt[(hc + 0) * QSTR + j] = k4.x; Kt[(hc + 1) * QSTR + j] = k4.y;
            Kt[(hc + 2) * QSTR + j] = k4.z; Kt[(hc + 3) * QSTR + j] = k4.w;
            float4 v4 = *reinterpret_cast<const float4*>(vb + (size_t)(j0g + j) * H + hc);
            *reinterpret_cast<float4*>(Vs + j * HSTR + hc) = v4;
        }
        __syncthreads();

        // S = Q @ K^T for this thread's 4x4 tile
        float s[4][4];
#pragma unroll
        for (int i = 0; i < 4; i++)
#pragma unroll
            for (int jj = 0; jj < 4; jj++) s[i][jj] = 0.f;

#pragma unroll 16
        for (int h = 0; h < H; h++) {
            float4 a = *reinterpret_cast<const float4*>(Qt + h * QSTR + r0);
            float4 bb = *reinterpret_cast<const float4*>(Kt + h * QSTR + c0);
            float av[4] = {a.x, a.y, a.z, a.w};
            float bv[4] = {bb.x, bb.y, bb.z, bb.w};
#pragma unroll
            for (int i = 0; i < 4; i++)
#pragma unroll
                for (int jj = 0; jj < 4; jj++)
                    s[i][jj] += av[i] * bv[jj];
        }

        // Scale + causal mask (only diagonal tile needs the mask)
        const bool last = (kt2 == nkv - 1);
#pragma unroll
        for (int i = 0; i < 4; i++)
#pragma unroll
            for (int jj = 0; jj < 4; jj++) {
                float v = s[i][jj] * SCALE;
                if (last && (j0g + c0 + jj > q0 + r0 + i)) v = -INFINITY;
                s[i][jj] = v;
            }

        // Online softmax: row stats across the 16 lanes sharing this row group
#pragma unroll
        for (int i = 0; i < 4; i++) {
            float rm = fmaxf(fmaxf(s[i][0], s[i][1]), fmaxf(s[i][2], s[i][3]));
#pragma unroll
            for (int off = 1; off < 16; off <<= 1)
                rm = fmaxf(rm, __shfl_xor_sync(0xFFFFFFFFu, rm, off));
            float mn = fmaxf(m_i[i], rm);
            float al = __expf(m_i[i] - mn);
            float ps = 0.f;
#pragma unroll
            for (int jj = 0; jj < 4; jj++) {
                float p = __expf(s[i][jj] - mn);
                s[i][jj] = p;
                ps += p;
            }
#pragma unroll
            for (int off = 1; off < 16; off <<= 1)
                ps += __shfl_xor_sync(0xFFFFFFFFu, ps, off);
            l_i[i] = l_i[i] * al + ps;
            m_i[i] = mn;
#pragma unroll
            for (int c = 0; c < 4; c++) o[i][c] *= al;
            // Stage P transposed: Pt[j][r]
#pragma unroll
            for (int jj = 0; jj < 4; jj++)
                Pt[(c0 + jj) * QSTR + r0 + i] = s[i][jj];
        }
        __syncthreads();

        // O += P @ V
#pragma unroll 16
        for (int j = 0; j < BKT; j++) {
            float4 pp = *reinterpret_cast<const float4*>(Pt + j * QSTR + r0);
            float4 vv = *reinterpret_cast<const float4*>(Vs + j * HSTR + c0);
            float pv[4] = {pp.x, pp.y, pp.z, pp.w};
            float vvv[4] = {vv.x, vv.y, vv.z, vv.w};
#pragma unroll
            for (int i = 0; i < 4; i++)
#pragma unroll
                for (int c = 0; c < 4; c++)
                    o[i][c] += pv[i] * vvv[c];
        }
    }

    // Epilogue: normalize and store
#pragma unroll
    for (int i = 0; i < 4; i++) {
        float inv = 1.f / l_i[i];
        float4 r = make_float4(o[i][0] * inv, o[i][1] * inv, o[i][2] * inv, o[i][3] * inv);
        *reinterpret_cast<float4*>(out + (size_t)(b * T + q0 + r0 + i) * H + c0) = r;
    }
}

extern "C" void kernel_launch(void* const* d_in, const int* in_sizes, int n_in,
                              void* d_out, int out_size) {
    const float* x  = (const float*)d_in[0];
    const float* Wk = (const float*)d_in[1];
    const float* Wv = (const float*)d_in[2];
    float* out = (float*)d_out;

    cudaFuncSetAttribute(attn_kernel, cudaFuncAttributeMaxDynamicSharedMemorySize, ATTN_SMEM);

    proj_kernel<<<(BATCH * T) / PBM, 256>>>(x, Wk, Wv);
    attn_kernel<<<dim3(T / BQ, BATCH), 256, ATTN_SMEM>>>(out);
}

// round 3
// speedup vs baseline: 2.5785x; 2.5785x over previous
#include <cuda_runtime.h>
#include <math.h>

#define BATCH 8
#define T 2048
#define C 1024
#define H 64

// Scratch for projected k and v: [B, T, H] fp32, 4 MB each.
__device__ float g_k[BATCH * T * H];
__device__ float g_v[BATCH * T * H];

__device__ __forceinline__ unsigned f2tf32(float x) {
    unsigned r;
    asm("cvt.rna.tf32.f32 %0, %1;" : "=r"(r) : "f"(x));
    return r;
}

__device__ __forceinline__ void mma_tf32(float* d,
                                         const unsigned* a,
                                         unsigned b0, unsigned b1) {
    asm volatile(
        "mma.sync.aligned.m16n8k8.row.col.f32.tf32.tf32.f32 "
        "{%0,%1,%2,%3}, {%4,%5,%6,%7}, {%8,%9}, {%0,%1,%2,%3};"
        : "+f"(d[0]), "+f"(d[1]), "+f"(d[2]), "+f"(d[3])
        : "r"(a[0]), "r"(a[1]), "r"(a[2]), "r"(a[3]), "r"(b0), "r"(b1));
}

// ---------------------------------------------------------------------------
// Projection: kv[m,n] = sum_c x[m,c] * W[n,c], W = concat(W_k, W_v), N=128.
// BM=128, BN=128(all), BK=32, 8 warps (2x4 warp grid: warp = 32m x 64n).
// ---------------------------------------------------------------------------
#define PBM 128
#define PBK 32
#define PSTR (PBK + 4)

__global__ void __launch_bounds__(256) proj_kernel(const float* __restrict__ x,
                                                   const float* __restrict__ Wk,
                                                   const float* __restrict__ Wv) {
    __shared__ unsigned As[PBM * PSTR];
    __shared__ unsigned Bs[128 * PSTR];

    const int tid = threadIdx.x;
    const int wid = tid >> 5;
    const int lane = tid & 31;
    const int g = lane >> 2;
    const int t = lane & 3;
    const int wr = wid >> 1;        // 0..3 : 32-row strip
    const int wc = wid & 1;         // 0..1 : 64-col strip
    const int m0 = blockIdx.x * PBM;

    float acc[2][8][4];
#pragma unroll
    for (int mf = 0; mf < 2; mf++)
#pragma unroll
        for (int nf = 0; nf < 8; nf++)
#pragma unroll
            for (int e = 0; e < 4; e++) acc[mf][nf][e] = 0.f;

    for (int k0 = 0; k0 < C; k0 += PBK) {
        // A: x[m0..m0+127][k0..k0+31] -> As[m][k] (tf32 bits)
#pragma unroll
        for (int l = 0; l < 4; l++) {
            int idx = tid + l * 256;           // 0..1023
            int m = idx >> 3;
            int kc = (idx & 7) * 4;
            float4 v = *reinterpret_cast<const float4*>(x + (size_t)(m0 + m) * C + k0 + kc);
            As[m * PSTR + kc + 0] = f2tf32(v.x);
            As[m * PSTR + kc + 1] = f2tf32(v.y);
            As[m * PSTR + kc + 2] = f2tf32(v.z);
            As[m * PSTR + kc + 3] = f2tf32(v.w);
        }
        // B: W[n][k0..k0+31] -> Bs[n][k]
#pragma unroll
        for (int l = 0; l < 4; l++) {
            int idx = tid + l * 256;
            int n = idx >> 3;
            int kc = (idx & 7) * 4;
            const float* wsrc = (n < 64) ? (Wk + (size_t)n * C) : (Wv + (size_t)(n - 64) * C);
            float4 v = *reinterpret_cast<const float4*>(wsrc + k0 + kc);
            Bs[n * PSTR + kc + 0] = f2tf32(v.x);
            Bs[n * PSTR + kc + 1] = f2tf32(v.y);
            Bs[n * PSTR + kc + 2] = f2tf32(v.z);
            Bs[n * PSTR + kc + 3] = f2tf32(v.w);
        }
        __syncthreads();

#pragma unroll
        for (int ks = 0; ks < 4; ks++) {
            const int kk = ks * 8;
            unsigned a[2][4];
#pragma unroll
            for (int mf = 0; mf < 2; mf++) {
                int r = wr * 32 + mf * 16;
                a[mf][0] = As[(r + g) * PSTR + kk + t];
                a[mf][1] = As[(r + g + 8) * PSTR + kk + t];
                a[mf][2] = As[(r + g) * PSTR + kk + t + 4];
                a[mf][3] = As[(r + g + 8) * PSTR + kk + t + 4];
            }
#pragma unroll
            for (int nf = 0; nf < 8; nf++) {
                int n = wc * 64 + nf * 8;
                unsigned b0 = Bs[(n + g) * PSTR + kk + t];
                unsigned b1 = Bs[(n + g) * PSTR + kk + t + 4];
#pragma unroll
                for (int mf = 0; mf < 2; mf++)
                    mma_tf32(acc[mf][nf], a[mf], b0, b1);
            }
        }
        __syncthreads();
    }

    // Epilogue: cols 0..63 -> g_k, 64..127 -> g_v (uniform per warp by wc)
    float* dst = (wc == 0) ? g_k : g_v;
#pragma unroll
    for (int mf = 0; mf < 2; mf++) {
        int r0 = m0 + wr * 32 + mf * 16;
#pragma unroll
        for (int nf = 0; nf < 8; nf++) {
            int col = nf * 8 + 2 * t;
            *reinterpret_cast<float2*>(dst + (size_t)(r0 + g) * H + col) =
                make_float2(acc[mf][nf][0], acc[mf][nf][1]);
            *reinterpret_cast<float2*>(dst + (size_t)(r0 + g + 8) * H + col) =
                make_float2(acc[mf][nf][2], acc[mf][nf][3]);
        }
    }
}

// ---------------------------------------------------------------------------
// Flash attention, tf32 mma. BQ=128 (8 warps x 16 rows), BK=64 per iter.
// Each warp owns full rows -> no cross-warp softmax reduction.
// ---------------------------------------------------------------------------
#define BQ 128
#define BK 64
#define KSTR 68
// smem: Ks[64][68] u32 + Vt[64][68] u32 + Ps[8 warps][16][68] f32
#define ATTN_SMEM ((64 * KSTR * 2 + 8 * 16 * KSTR) * 4)

__global__ void __launch_bounds__(256) attn_kernel(float* __restrict__ out) {
    extern __shared__ unsigned char smraw[];
    unsigned* Ks = reinterpret_cast<unsigned*>(smraw);       // [j][h]
    unsigned* Vt = Ks + 64 * KSTR;                           // [h][j]  (V transposed)
    float* PsAll = reinterpret_cast<float*>(Vt + 64 * KSTR); // [warp][16][68]

    const int tid = threadIdx.x;
    const int wid = tid >> 5;
    const int lane = tid & 31;
    const int g = lane >> 2;
    const int t = lane & 3;
    const int b = blockIdx.y;
    const int qt = (int)gridDim.x - 1 - (int)blockIdx.x;  // heavy tiles first
    const int q0 = qt * BQ;

    float* Ps = PsAll + wid * 16 * KSTR;

    const float* kb = g_k + (size_t)b * T * H;
    const float* vb = g_v + (size_t)b * T * H;

    // Q fragments: rows q0 + wid*16 + {g, g+8}, resident for the whole CTA.
    const int qra = q0 + wid * 16 + g;
    const int qrb = qra + 8;
    unsigned qa[8][4];
#pragma unroll
    for (int kf = 0; kf < 8; kf++) {
        qa[kf][0] = f2tf32(kb[(size_t)qra * H + kf * 8 + t]);
        qa[kf][1] = f2tf32(kb[(size_t)qrb * H + kf * 8 + t]);
        qa[kf][2] = f2tf32(kb[(size_t)qra * H + kf * 8 + t + 4]);
        qa[kf][3] = f2tf32(kb[(size_t)qrb * H + kf * 8 + t + 4]);
    }

    float o[8][4];
#pragma unroll
    for (int nf = 0; nf < 8; nf++)
#pragma unroll
        for (int e = 0; e < 4; e++) o[nf][e] = 0.f;
    float m_i[2] = {-INFINITY, -INFINITY};
    float l_i[2] = {0.f, 0.f};

    const float SCALE = 0.125f;  // 64^-0.5
    const int nkv = 2 * qt + 2;

    for (int kt2 = 0; kt2 < nkv; kt2++) {
        const int j0g = kt2 * BK;
        __syncthreads();  // protect Ks/Vt against previous-iteration readers

        // Stage K -> Ks[j][h], V -> Vt[h][j] (tf32 bits)
#pragma unroll
        for (int l = 0; l < 4; l++) {
            int idx = tid + l * 256;       // 0..1023
            int j = idx >> 4;              // 0..63
            int hc = (idx & 15) * 4;       // 0..60
            float4 k4 = *reinterpret_cast<const float4*>(kb + (size_t)(j0g + j) * H + hc);
            Ks[j * KSTR + hc + 0] = f2tf32(k4.x);
            Ks[j * KSTR + hc + 1] = f2tf32(k4.y);
            Ks[j * KSTR + hc + 2] = f2tf32(k4.z);
            Ks[j * KSTR + hc + 3] = f2tf32(k4.w);
            float4 v4 = *reinterpret_cast<const float4*>(vb + (size_t)(j0g + j) * H + hc);
            Vt[(hc + 0) * KSTR + j] = f2tf32(v4.x);
            Vt[(hc + 1) * KSTR + j] = f2tf32(v4.y);
            Vt[(hc + 2) * KSTR + j] = f2tf32(v4.z);
            Vt[(hc + 3) * KSTR + j] = f2tf32(v4.w);
        }
        __syncthreads();

        // S = Q @ K^T  (per-warp 16x64)
        float s[8][4];
#pragma unroll
        for (int nf = 0; nf < 8; nf++)
#pragma unroll
            for (int e = 0; e < 4; e++) s[nf][e] = 0.f;

#pragma unroll
        for (int kf = 0; kf < 8; kf++) {
            const int kk = kf * 8;
#pragma unroll
            for (int nf = 0; nf < 8; nf++) {
                unsigned b0 = Ks[(nf * 8 + g) * KSTR + kk + t];
                unsigned b1 = Ks[(nf * 8 + g) * KSTR + kk + t + 4];
                mma_tf32(s[nf], qa[kf], b0, b1);
            }
        }

        // Scale + causal mask (only the last two kv tiles intersect the diagonal)
        const bool needm = (kt2 >= 2 * qt);
#pragma unroll
        for (int nf = 0; nf < 8; nf++)
#pragma unroll
            for (int e = 0; e < 4; e++) {
                int col = j0g + nf * 8 + 2 * t + (e & 1);
                int row = (e & 2) ? qrb : qra;
                float v = s[nf][e] * SCALE;
                if (needm && col > row) v = -INFINITY;
                s[nf][e] = v;
            }

        // Online softmax per row half (rows qra, qrb)
#pragma unroll
        for (int h2 = 0; h2 < 2; h2++) {
            const int e0 = h2 * 2;
            float rm = -INFINITY;
#pragma unroll
            for (int nf = 0; nf < 8; nf++)
                rm = fmaxf(rm, fmaxf(s[nf][e0], s[nf][e0 + 1]));
            rm = fmaxf(rm, __shfl_xor_sync(0xFFFFFFFFu, rm, 1));
            rm = fmaxf(rm, __shfl_xor_sync(0xFFFFFFFFu, rm, 2));
            float mn = fmaxf(m_i[h2], rm);
            float al = __expf(m_i[h2] - mn);
            float ps = 0.f;
#pragma unroll
            for (int nf = 0; nf < 8; nf++) {
                float p0 = __expf(s[nf][e0] - mn);
                float p1 = __expf(s[nf][e0 + 1] - mn);
                ps += p0 + p1;
                o[nf][e0] *= al;
                o[nf][e0 + 1] *= al;
                *reinterpret_cast<float2*>(Ps + (g + 8 * h2) * KSTR + nf * 8 + 2 * t) =
                    make_float2(p0, p1);
            }
            ps += __shfl_xor_sync(0xFFFFFFFFu, ps, 1);
            ps += __shfl_xor_sync(0xFFFFFFFFu, ps, 2);
            l_i[h2] = l_i[h2] * al + ps;
            m_i[h2] = mn;
        }
        __syncwarp();

        // O += P @ V  (A = P from warp-private smem, B = V^T staged)
#pragma unroll
        for (int kf = 0; kf < 8; kf++) {
            const int kk = kf * 8;
            unsigned a[4];
            a[0] = f2tf32(Ps[g * KSTR + kk + t]);
            a[1] = f2tf32(Ps[(g + 8) * KSTR + kk + t]);
            a[2] = f2tf32(Ps[g * KSTR + kk + t + 4]);
            a[3] = f2tf32(Ps[(g + 8) * KSTR + kk + t + 4]);
#pragma unroll
            for (int nf = 0; nf < 8; nf++) {
                unsigned b0 = Vt[(nf * 8 + g) * KSTR + kk + t];
                unsigned b1 = Vt[(nf * 8 + g) * KSTR + kk + t + 4];
                mma_tf32(o[nf], a, b0, b1);
            }
        }
    }

    // Epilogue
    const float inva = 1.f / l_i[0];
    const float invb = 1.f / l_i[1];
    float* ob = out + (size_t)b * T * H;
#pragma unroll
    for (int nf = 0; nf < 8; nf++) {
        int col = nf * 8 + 2 * t;
        *reinterpret_cast<float2*>(ob + (size_t)qra * H + col) =
            make_float2(o[nf][0] * inva, o[nf][1] * inva);
        *reinterpret_cast<float2*>(ob + (size_t)qrb * H + col) =
            make_float2(o[nf][2] * invb, o[nf][3] * invb);
    }
}

extern "C" void kernel_launch(void* const* d_in, const int* in_sizes, int n_in,
                              void* d_out, int out_size) {
    const float* x  = (const float*)d_in[0];
    const float* Wk = (const float*)d_in[1];
    const float* Wv = (const float*)d_in[2];
    float* out = (float*)d_out;

    cudaFuncSetAttribute(attn_kernel, cudaFuncAttributeMaxDynamicSharedMemorySize, ATTN_SMEM);

    proj_kernel<<<(BATCH * T) / PBM, 256>>>(x, Wk, Wv);
    attn_kernel<<<dim3(T / BQ, BATCH), 256, ATTN_SMEM>>>(out);
}

// round 4
// speedup vs baseline: 2.6499x; 1.0277x over previous
#include <cuda_runtime.h>
#include <math.h>

#define BATCH 8
#define T 2048
#define C 1024
#define H 64

// Scratch for projected k and v: [B, T, H] fp32, 4 MB each.
__device__ float g_k[BATCH * T * H];
__device__ float g_v[BATCH * T * H];

__device__ __forceinline__ unsigned f2tf32(float x) {
    unsigned r;
    asm("cvt.rna.tf32.f32 %0, %1;" : "=r"(r) : "f"(x));
    return r;
}

__device__ __forceinline__ void mma_tf32(float* d,
                                         const unsigned* a,
                                         unsigned b0, unsigned b1) {
    asm volatile(
        "mma.sync.aligned.m16n8k8.row.col.f32.tf32.tf32.f32 "
        "{%0,%1,%2,%3}, {%4,%5,%6,%7}, {%8,%9}, {%0,%1,%2,%3};"
        : "+f"(d[0]), "+f"(d[1]), "+f"(d[2]), "+f"(d[3])
        : "r"(a[0]), "r"(a[1]), "r"(a[2]), "r"(a[3]), "r"(b0), "r"(b1));
}

// ---------------------------------------------------------------------------
// Projection: kv[m,n] = sum_c x[m,c] * W[n,c], W = concat(W_k, W_v), N=128.
// BM=128, BN=128(all), BK=32, 8 warps. Register double-buffered global loads.
// ---------------------------------------------------------------------------
#define PBM 128
#define PBK 32
#define PSTR (PBK + 4)

__global__ void __launch_bounds__(256) proj_kernel(const float* __restrict__ x,
                                                   const float* __restrict__ Wk,
                                                   const float* __restrict__ Wv) {
    __shared__ unsigned As[PBM * PSTR];
    __shared__ unsigned Bs[128 * PSTR];

    const int tid = threadIdx.x;
    const int wid = tid >> 5;
    const int lane = tid & 31;
    const int g = lane >> 2;
    const int t = lane & 3;
    const int wr = wid >> 1;        // 0..3 : 32-row strip
    const int wc = wid & 1;         // 0..1 : 64-col strip
    const int m0 = blockIdx.x * PBM;

    // Per-thread load slots: A tile 128x32 = 1024 float4, B same -> 4 each.
    const int am[4] = { (tid + 0) >> 3, (tid + 256) >> 3, (tid + 512) >> 3, (tid + 768) >> 3 };
    const int ak = (tid & 7) * 4;
    const float* bsrc[4];
#pragma unroll
    for (int l = 0; l < 4; l++) {
        int n = (tid + l * 256) >> 3;
        bsrc[l] = (n < 64) ? (Wk + (size_t)n * C) : (Wv + (size_t)(n - 64) * C);
    }

    float4 pa[4], pb[4];
#pragma unroll
    for (int l = 0; l < 4; l++) {
        pa[l] = *reinterpret_cast<const float4*>(x + (size_t)(m0 + am[l]) * C + ak);
        pb[l] = *reinterpret_cast<const float4*>(bsrc[l] + ak);
    }

    float acc[2][8][4];
#pragma unroll
    for (int mf = 0; mf < 2; mf++)
#pragma unroll
        for (int nf = 0; nf < 8; nf++)
#pragma unroll
            for (int e = 0; e < 4; e++) acc[mf][nf][e] = 0.f;

    for (int k0 = 0; k0 < C; k0 += PBK) {
        // Stage prefetched tile (cvt to tf32)
#pragma unroll
        for (int l = 0; l < 4; l++) {
            int m = am[l];
            As[m * PSTR + ak + 0] = f2tf32(pa[l].x);
            As[m * PSTR + ak + 1] = f2tf32(pa[l].y);
            As[m * PSTR + ak + 2] = f2tf32(pa[l].z);
            As[m * PSTR + ak + 3] = f2tf32(pa[l].w);
            Bs[m * PSTR + ak + 0] = f2tf32(pb[l].x);
            Bs[m * PSTR + ak + 1] = f2tf32(pb[l].y);
            Bs[m * PSTR + ak + 2] = f2tf32(pb[l].z);
            Bs[m * PSTR + ak + 3] = f2tf32(pb[l].w);
        }
        __syncthreads();

        // Prefetch next tile (overlaps with compute below)
        if (k0 + PBK < C) {
#pragma unroll
            for (int l = 0; l < 4; l++) {
                pa[l] = *reinterpret_cast<const float4*>(x + (size_t)(m0 + am[l]) * C + k0 + PBK + ak);
                pb[l] = *reinterpret_cast<const float4*>(bsrc[l] + k0 + PBK + ak);
            }
        }

#pragma unroll
        for (int ks = 0; ks < 4; ks++) {
            const int kk = ks * 8;
            unsigned a[2][4];
#pragma unroll
            for (int mf = 0; mf < 2; mf++) {
                int r = wr * 32 + mf * 16;
                a[mf][0] = As[(r + g) * PSTR + kk + t];
                a[mf][1] = As[(r + g + 8) * PSTR + kk + t];
                a[mf][2] = As[(r + g) * PSTR + kk + t + 4];
                a[mf][3] = As[(r + g + 8) * PSTR + kk + t + 4];
            }
#pragma unroll
            for (int nf = 0; nf < 8; nf++) {
                int n = wc * 64 + nf * 8;
                unsigned b0 = Bs[(n + g) * PSTR + kk + t];
                unsigned b1 = Bs[(n + g) * PSTR + kk + t + 4];
#pragma unroll
                for (int mf = 0; mf < 2; mf++)
                    mma_tf32(acc[mf][nf], a[mf], b0, b1);
            }
        }
        __syncthreads();
    }

    float* dst = (wc == 0) ? g_k : g_v;
#pragma unroll
    for (int mf = 0; mf < 2; mf++) {
        int r0 = m0 + wr * 32 + mf * 16;
#pragma unroll
        for (int nf = 0; nf < 8; nf++) {
            int col = nf * 8 + 2 * t;
            *reinterpret_cast<float2*>(dst + (size_t)(r0 + g) * H + col) =
                make_float2(acc[mf][nf][0], acc[mf][nf][1]);
            *reinterpret_cast<float2*>(dst + (size_t)(r0 + g + 8) * H + col) =
                make_float2(acc[mf][nf][2], acc[mf][nf][3]);
        }
    }
}

// ---------------------------------------------------------------------------
// Flash attention, tf32 mma. BQ=64 (4 warps x 16 rows), BK=64 per iter.
// 256 CTAs, ~2 co-resident per SM; heavy q-tiles launch first.
// ---------------------------------------------------------------------------
#define BQ 64
#define BK 64
#define KSTR 68
// smem: Ks[64][68] u32 + Vt[64][68] u32 + Ps[4 warps][16][68] f32 = 51 KB
#define ATTN_SMEM ((64 * KSTR * 2 + 4 * 16 * KSTR) * 4)

__global__ void __launch_bounds__(128, 2) attn_kernel(float* __restrict__ out) {
    extern __shared__ unsigned char smraw[];
    unsigned* Ks = reinterpret_cast<unsigned*>(smraw);       // [j][h]
    unsigned* Vt = Ks + 64 * KSTR;                           // [h][j]  (V transposed)
    float* PsAll = reinterpret_cast<float*>(Vt + 64 * KSTR); // [warp][16][68]

    const int tid = threadIdx.x;
    const int wid = tid >> 5;
    const int lane = tid & 31;
    const int g = lane >> 2;
    const int t = lane & 3;
    const int b = blockIdx.y;
    const int qt = (int)gridDim.x - 1 - (int)blockIdx.x;  // heavy tiles first
    const int q0 = qt * BQ;

    float* Ps = PsAll + wid * 16 * KSTR;

    const float* kb = g_k + (size_t)b * T * H;
    const float* vb = g_v + (size_t)b * T * H;

    // Q fragments: rows q0 + wid*16 + {g, g+8}, resident for the whole CTA.
    const int qra = q0 + wid * 16 + g;
    const int qrb = qra + 8;
    unsigned qa[8][4];
#pragma unroll
    for (int kf = 0; kf < 8; kf++) {
        qa[kf][0] = f2tf32(kb[(size_t)qra * H + kf * 8 + t]);
        qa[kf][1] = f2tf32(kb[(size_t)qrb * H + kf * 8 + t]);
        qa[kf][2] = f2tf32(kb[(size_t)qra * H + kf * 8 + t + 4]);
        qa[kf][3] = f2tf32(kb[(size_t)qrb * H + kf * 8 + t + 4]);
    }

    float o[8][4];
#pragma unroll
    for (int nf = 0; nf < 8; nf++)
#pragma unroll
        for (int e = 0; e < 4; e++) o[nf][e] = 0.f;
    float m_i[2] = {-INFINITY, -INFINITY};
    float l_i[2] = {0.f, 0.f};

    const float SCALE = 0.125f;  // 64^-0.5
    const int nkv = qt + 1;

    for (int kt2 = 0; kt2 < nkv; kt2++) {
        const int j0g = kt2 * BK;
        __syncthreads();  // protect Ks/Vt against previous-iteration readers

        // Stage K -> Ks[j][h], V -> Vt[h][j] (tf32 bits). 1024 chunks / 128 thr.
#pragma unroll
        for (int l = 0; l < 8; l++) {
            int idx = tid + l * 128;       // 0..1023
            int j = idx >> 4;              // 0..63
            int hc = (idx & 15) * 4;       // 0..60
            float4 k4 = *reinterpret_cast<const float4*>(kb + (size_t)(j0g + j) * H + hc);
            Ks[j * KSTR + hc + 0] = f2tf32(k4.x);
            Ks[j * KSTR + hc + 1] = f2tf32(k4.y);
            Ks[j * KSTR + hc + 2] = f2tf32(k4.z);
            Ks[j * KSTR + hc + 3] = f2tf32(k4.w);
            float4 v4 = *reinterpret_cast<const float4*>(vb + (size_t)(j0g + j) * H + hc);
            Vt[(hc + 0) * KSTR + j] = f2tf32(v4.x);
            Vt[(hc + 1) * KSTR + j] = f2tf32(v4.y);
            Vt[(hc + 2) * KSTR + j] = f2tf32(v4.z);
            Vt[(hc + 3) * KSTR + j] = f2tf32(v4.w);
        }
        __syncthreads();

        // S = Q @ K^T  (per-warp 16x64)
        float s[8][4];
#pragma unroll
        for (int nf = 0; nf < 8; nf++)
#pragma unroll
            for (int e = 0; e < 4; e++) s[nf][e] = 0.f;

#pragma unroll
        for (int kf = 0; kf < 8; kf++) {
            const int kk = kf * 8;
#pragma unroll
            for (int nf = 0; nf < 8; nf++) {
                unsigned b0 = Ks[(nf * 8 + g) * KSTR + kk + t];
                unsigned b1 = Ks[(nf * 8 + g) * KSTR + kk + t + 4];
                mma_tf32(s[nf], qa[kf], b0, b1);
            }
        }

        // Scale + causal mask (only the diagonal tile needs the mask)
        const bool needm = (kt2 == nkv - 1);
#pragma unroll
        for (int nf = 0; nf < 8; nf++)
#pragma unroll
            for (int e = 0; e < 4; e++) {
                int col = j0g + nf * 8 + 2 * t + (e & 1);
                int row = (e & 2) ? qrb : qra;
                float v = s[nf][e] * SCALE;
                if (needm && col > row) v = -INFINITY;
                s[nf][e] = v;
            }

        // Online softmax per row half (rows qra, qrb)
#pragma unroll
        for (int h2 = 0; h2 < 2; h2++) {
            const int e0 = h2 * 2;
            float rm = -INFINITY;
#pragma unroll
            for (int nf = 0; nf < 8; nf++)
                rm = fmaxf(rm, fmaxf(s[nf][e0], s[nf][e0 + 1]));
            rm = fmaxf(rm, __shfl_xor_sync(0xFFFFFFFFu, rm, 1));
            rm = fmaxf(rm, __shfl_xor_sync(0xFFFFFFFFu, rm, 2));
            float mn = fmaxf(m_i[h2], rm);
            float al = __expf(m_i[h2] - mn);
            float ps = 0.f;
#pragma unroll
            for (int nf = 0; nf < 8; nf++) {
                float p0 = __expf(s[nf][e0] - mn);
                float p1 = __expf(s[nf][e0 + 1] - mn);
                ps += p0 + p1;
                o[nf][e0] *= al;
                o[nf][e0 + 1] *= al;
                *reinterpret_cast<float2*>(Ps + (g + 8 * h2) * KSTR + nf * 8 + 2 * t) =
                    make_float2(p0, p1);
            }
            ps += __shfl_xor_sync(0xFFFFFFFFu, ps, 1);
            ps += __shfl_xor_sync(0xFFFFFFFFu, ps, 2);
            l_i[h2] = l_i[h2] * al + ps;
            m_i[h2] = mn;
        }
        __syncwarp();

        // O += P @ V  (A = P from warp-private smem, B = V^T staged)
#pragma unroll
        for (int kf = 0; kf < 8; kf++) {
            const int kk = kf * 8;
            unsigned a[4];
            a[0] = f2tf32(Ps[g * KSTR + kk + t]);
            a[1] = f2tf32(Ps[(g + 8) * KSTR + kk + t]);
            a[2] = f2tf32(Ps[g * KSTR + kk + t + 4]);
            a[3] = f2tf32(Ps[(g + 8) * KSTR + kk + t + 4]);
#pragma unroll
            for (int nf = 0; nf < 8; nf++) {
                unsigned b0 = Vt[(nf * 8 + g) * KSTR + kk + t];
                unsigned b1 = Vt[(nf * 8 + g) * KSTR + kk + t + 4];
                mma_tf32(o[nf], a, b0, b1);
            }
        }
    }

    // Epilogue
    const float inva = 1.f / l_i[0];
    const float invb = 1.f / l_i[1];
    float* ob = out + (size_t)b * T * H;
#pragma unroll
    for (int nf = 0; nf < 8; nf++) {
        int col = nf * 8 + 2 * t;
        *reinterpret_cast<float2*>(ob + (size_t)qra * H + col) =
            make_float2(o[nf][0] * inva, o[nf][1] * inva);
        *reinterpret_cast<float2*>(ob + (size_t)qrb * H + col) =
            make_float2(o[nf][2] * invb, o[nf][3] * invb);
    }
}

extern "C" void kernel_launch(void* const* d_in, const int* in_sizes, int n_in,
                              void* d_out, int out_size) {
    const float* x  = (const float*)d_in[0];
    const float* Wk = (const float*)d_in[1];
    const float* Wv = (const float*)d_in[2];
    float* out = (float*)d_out;

    cudaFuncSetAttribute(attn_kernel, cudaFuncAttributeMaxDynamicSharedMemorySize, ATTN_SMEM);

    proj_kernel<<<(BATCH * T) / PBM, 256>>>(x, Wk, Wv);
    attn_kernel<<<dim3(T / BQ, BATCH), 128, ATTN_SMEM>>>(out);
}

// round 5
// speedup vs baseline: 4.1104x; 1.5512x over previous
#include <cuda_runtime.h>
#include <math.h>

#define BATCH 8
#define T 2048
#define C 1024
#define H 64

// Scratch: projected k,v and split-KV partials.
__device__ float g_k[BATCH * T * H];
__device__ float g_v[BATCH * T * H];
#define NCHUNK 4
__device__ float g_po[BATCH * NCHUNK * T * H];   // [b][c][row][h], unnormalized
__device__ float g_pm[BATCH * T * NCHUNK];       // base-2 running max
__device__ float g_pl[BATCH * T * NCHUNK];       // running denom

__device__ __forceinline__ unsigned f2tf32(float x) {
    unsigned r;
    asm("cvt.rna.tf32.f32 %0, %1;" : "=r"(r) : "f"(x));
    return r;
}

__device__ __forceinline__ void mma_tf32(float* d,
                                         const unsigned* a,
                                         unsigned b0, unsigned b1) {
    asm volatile(
        "mma.sync.aligned.m16n8k8.row.col.f32.tf32.tf32.f32 "
        "{%0,%1,%2,%3}, {%4,%5,%6,%7}, {%8,%9}, {%0,%1,%2,%3};"
        : "+f"(d[0]), "+f"(d[1]), "+f"(d[2]), "+f"(d[3])
        : "r"(a[0]), "r"(a[1]), "r"(a[2]), "r"(a[3]), "r"(b0), "r"(b1));
}

// ---------------------------------------------------------------------------
// Projection: kv[m,n] = sum_c x[m,c] * W[n,c]. BM=64, BN=128, BK=32.
// 256 threads, 8 warps (4 row-strips x 2 col-halves). Grid 256 -> multi-CTA/SM.
// ---------------------------------------------------------------------------
#define PBM 64
#define PBK 32
#define PSTR (PBK + 4)

__global__ void __launch_bounds__(256) proj_kernel(const float* __restrict__ x,
                                                   const float* __restrict__ Wk,
                                                   const float* __restrict__ Wv) {
    __shared__ unsigned As[PBM * PSTR];
    __shared__ unsigned Bs[128 * PSTR];

    const int tid = threadIdx.x;
    const int wid = tid >> 5;
    const int lane = tid & 31;
    const int g = lane >> 2;
    const int t = lane & 3;
    const int wr = wid >> 1;        // 0..3 : 16-row strip
    const int wc = wid & 1;         // 0..1 : 64-col half
    const int m0 = blockIdx.x * PBM;

    // A: 64x32 = 512 float4 -> 2/thread. B: 128x32 = 1024 float4 -> 4/thread.
    const int am[2] = { (tid + 0) >> 3, (tid + 256) >> 3 };       // 0..63
    const int ak = (tid & 7) * 4;
    const int bn[4] = { (tid + 0) >> 3, (tid + 256) >> 3, (tid + 512) >> 3, (tid + 768) >> 3 };
    const float* bsrc[4];
#pragma unroll
    for (int l = 0; l < 4; l++)
        bsrc[l] = (bn[l] < 64) ? (Wk + (size_t)bn[l] * C) : (Wv + (size_t)(bn[l] - 64) * C);

    float4 pa[2], pb[4];
#pragma unroll
    for (int l = 0; l < 2; l++)
        pa[l] = *reinterpret_cast<const float4*>(x + (size_t)(m0 + am[l]) * C + ak);
#pragma unroll
    for (int l = 0; l < 4; l++)
        pb[l] = *reinterpret_cast<const float4*>(bsrc[l] + ak);

    float acc[8][4];
#pragma unroll
    for (int nf = 0; nf < 8; nf++)
#pragma unroll
        for (int e = 0; e < 4; e++) acc[nf][e] = 0.f;

    for (int k0 = 0; k0 < C; k0 += PBK) {
#pragma unroll
        for (int l = 0; l < 2; l++) {
            As[am[l] * PSTR + ak + 0] = f2tf32(pa[l].x);
            As[am[l] * PSTR + ak + 1] = f2tf32(pa[l].y);
            As[am[l] * PSTR + ak + 2] = f2tf32(pa[l].z);
            As[am[l] * PSTR + ak + 3] = f2tf32(pa[l].w);
        }
#pragma unroll
        for (int l = 0; l < 4; l++) {
            Bs[bn[l] * PSTR + ak + 0] = f2tf32(pb[l].x);
            Bs[bn[l] * PSTR + ak + 1] = f2tf32(pb[l].y);
            Bs[bn[l] * PSTR + ak + 2] = f2tf32(pb[l].z);
            Bs[bn[l] * PSTR + ak + 3] = f2tf32(pb[l].w);
        }
        __syncthreads();

        if (k0 + PBK < C) {
#pragma unroll
            for (int l = 0; l < 2; l++)
                pa[l] = *reinterpret_cast<const float4*>(x + (size_t)(m0 + am[l]) * C + k0 + PBK + ak);
#pragma unroll
            for (int l = 0; l < 4; l++)
                pb[l] = *reinterpret_cast<const float4*>(bsrc[l] + k0 + PBK + ak);
        }

#pragma unroll
        for (int ks = 0; ks < 4; ks++) {
            const int kk = ks * 8;
            unsigned a[4];
            const int r = wr * 16;
            a[0] = As[(r + g) * PSTR + kk + t];
            a[1] = As[(r + g + 8) * PSTR + kk + t];
            a[2] = As[(r + g) * PSTR + kk + t + 4];
            a[3] = As[(r + g + 8) * PSTR + kk + t + 4];
#pragma unroll
            for (int nf = 0; nf < 8; nf++) {
                int n = wc * 64 + nf * 8;
                unsigned b0 = Bs[(n + g) * PSTR + kk + t];
                unsigned b1 = Bs[(n + g) * PSTR + kk + t + 4];
                mma_tf32(acc[nf], a, b0, b1);
            }
        }
        __syncthreads();
    }

    float* dst = (wc == 0) ? g_k : g_v;
    const int r0 = m0 + wr * 16;
#pragma unroll
    for (int nf = 0; nf < 8; nf++) {
        int col = nf * 8 + 2 * t;
        *reinterpret_cast<float2*>(dst + (size_t)(r0 + g) * H + col) =
            make_float2(acc[nf][0], acc[nf][1]);
        *reinterpret_cast<float2*>(dst + (size_t)(r0 + g + 8) * H + col) =
            make_float2(acc[nf][2], acc[nf][3]);
    }
}

// ---------------------------------------------------------------------------
// Attention pass 1: split-KV. CTA = (qt, chunk, b); BQ=64 (4 warps x 16 rows),
// chunk = up to 8 kv-tiles of BK=64. Writes unnormalized partials.
// ---------------------------------------------------------------------------
#define BQ 64
#define BK 64
#define KSTR 68
#define VSTR 72
#define CHUNK_TILES 8
// smem: Ks[64][68] + Vs[64][72] (u32) + Ps[4][16][68] (f32)
#define ATTN_SMEM ((64 * KSTR + 64 * VSTR + 4 * 16 * KSTR) * 4)
#define LOG2E 1.4426950408889634f

__global__ void __launch_bounds__(128) attn_chunk_kernel() {
    const int qt = 31 - (int)blockIdx.x;   // heavy-first
    const int chunk = blockIdx.y;
    if (chunk * CHUNK_TILES > qt) return;
    const int b = blockIdx.z;

    extern __shared__ unsigned char smraw[];
    unsigned* Ks = reinterpret_cast<unsigned*>(smraw);       // [j][h] stride 68
    unsigned* Vs = Ks + 64 * KSTR;                           // [j][h] stride 72
    float* PsAll = reinterpret_cast<float*>(Vs + 64 * VSTR); // [warp][16][68]

    const int tid = threadIdx.x;
    const int wid = tid >> 5;
    const int lane = tid & 31;
    const int g = lane >> 2;
    const int t = lane & 3;
    const int q0 = qt * BQ;

    float* Ps = PsAll + wid * 16 * KSTR;
    const float* kb = g_k + (size_t)b * T * H;
    const float* vb = g_v + (size_t)b * T * H;

    const int kt0 = chunk * CHUNK_TILES;
    const int ktend = min(qt, kt0 + CHUNK_TILES - 1);
    const int niter = ktend - kt0 + 1;

    // Q fragments (rows q0 + wid*16 + {g, g+8}), resident.
    const int qra = q0 + wid * 16 + g;
    const int qrb = qra + 8;
    unsigned qa[8][4];
#pragma unroll
    for (int kf = 0; kf < 8; kf++) {
        qa[kf][0] = f2tf32(kb[(size_t)qra * H + kf * 8 + t]);
        qa[kf][1] = f2tf32(kb[(size_t)qrb * H + kf * 8 + t]);
        qa[kf][2] = f2tf32(kb[(size_t)qra * H + kf * 8 + t + 4]);
        qa[kf][3] = f2tf32(kb[(size_t)qrb * H + kf * 8 + t + 4]);
    }

    // Staging slots: 8 chunks of (j, hc) per thread for 64x64 tile.
    const int sj = tid >> 4;          // base j advances by 8 per l
    const int shc = (tid & 15) * 4;

    float4 pk[8], pv[8];
    {
        const int j0g = kt0 * BK;
#pragma unroll
        for (int l = 0; l < 8; l++) {
            int j = sj + l * 8;
            pk[l] = *reinterpret_cast<const float4*>(kb + (size_t)(j0g + j) * H + shc);
            pv[l] = *reinterpret_cast<const float4*>(vb + (size_t)(j0g + j) * H + shc);
        }
    }

    float o[8][4];
#pragma unroll
    for (int nf = 0; nf < 8; nf++)
#pragma unroll
        for (int e = 0; e < 4; e++) o[nf][e] = 0.f;
    float m_i[2] = {-INFINITY, -INFINITY};
    float l_i[2] = {0.f, 0.f};

    const float S2 = 0.125f * LOG2E;   // scale folded into base-2 domain

    for (int it = 0; it < niter; it++) {
        const int kvt = kt0 + it;
        const int j0g = kvt * BK;

        // Stage prefetched K/V (cvt to tf32)
#pragma unroll
        for (int l = 0; l < 8; l++) {
            int j = sj + l * 8;
            Ks[j * KSTR + shc + 0] = f2tf32(pk[l].x);
            Ks[j * KSTR + shc + 1] = f2tf32(pk[l].y);
            Ks[j * KSTR + shc + 2] = f2tf32(pk[l].z);
            Ks[j * KSTR + shc + 3] = f2tf32(pk[l].w);
            Vs[j * VSTR + shc + 0] = f2tf32(pv[l].x);
            Vs[j * VSTR + shc + 1] = f2tf32(pv[l].y);
            Vs[j * VSTR + shc + 2] = f2tf32(pv[l].z);
            Vs[j * VSTR + shc + 3] = f2tf32(pv[l].w);
        }
        __syncthreads();

        // Prefetch next tile (latency hidden under MMA/softmax)
        if (it + 1 < niter) {
            const int jn = (kvt + 1) * BK;
#pragma unroll
            for (int l = 0; l < 8; l++) {
                int j = sj + l * 8;
                pk[l] = *reinterpret_cast<const float4*>(kb + (size_t)(jn + j) * H + shc);
                pv[l] = *reinterpret_cast<const float4*>(vb + (size_t)(jn + j) * H + shc);
            }
        }

        // S = Q @ K^T (16x64 per warp)
        float s[8][4];
#pragma unroll
        for (int nf = 0; nf < 8; nf++)
#pragma unroll
            for (int e = 0; e < 4; e++) s[nf][e] = 0.f;
#pragma unroll
        for (int kf = 0; kf < 8; kf++) {
            const int kk = kf * 8;
#pragma unroll
            for (int nf = 0; nf < 8; nf++) {
                unsigned b0 = Ks[(nf * 8 + g) * KSTR + kk + t];
                unsigned b1 = Ks[(nf * 8 + g) * KSTR + kk + t + 4];
                mma_tf32(s[nf], qa[kf], b0, b1);
            }
        }

        // base-2 scale + causal mask (diagonal tile only)
        const bool needm = (kvt == qt);
#pragma unroll
        for (int nf = 0; nf < 8; nf++)
#pragma unroll
            for (int e = 0; e < 4; e++) {
                int col = j0g + nf * 8 + 2 * t + (e & 1);
                int row = (e & 2) ? qrb : qra;
                float v = s[nf][e] * S2;
                if (needm && col > row) v = -INFINITY;
                s[nf][e] = v;
            }

        // Online softmax (base 2) per row half
#pragma unroll
        for (int h2 = 0; h2 < 2; h2++) {
            const int e0 = h2 * 2;
            float rm = -INFINITY;
#pragma unroll
            for (int nf = 0; nf < 8; nf++)
                rm = fmaxf(rm, fmaxf(s[nf][e0], s[nf][e0 + 1]));
            rm = fmaxf(rm, __shfl_xor_sync(0xFFFFFFFFu, rm, 1));
            rm = fmaxf(rm, __shfl_xor_sync(0xFFFFFFFFu, rm, 2));
            float mn = fmaxf(m_i[h2], rm);
            float al = exp2f(m_i[h2] - mn);
            float ps = 0.f;
#pragma unroll
            for (int nf = 0; nf < 8; nf++) {
                float p0 = exp2f(s[nf][e0] - mn);
                float p1 = exp2f(s[nf][e0 + 1] - mn);
                ps += p0 + p1;
                o[nf][e0] *= al;
                o[nf][e0 + 1] *= al;
                *reinterpret_cast<float2*>(Ps + (g + 8 * h2) * KSTR + nf * 8 + 2 * t) =
                    make_float2(p0, p1);
            }
            ps += __shfl_xor_sync(0xFFFFFFFFu, ps, 1);
            ps += __shfl_xor_sync(0xFFFFFFFFu, ps, 2);
            l_i[h2] = l_i[h2] * al + ps;
            m_i[h2] = mn;
        }
        __syncwarp();

        // O += P @ V   (B-frags straight from row-major Vs: b0 = V[kk+t][n0+g])
#pragma unroll
        for (int kf = 0; kf < 8; kf++) {
            const int kk = kf * 8;
            unsigned a[4];
            a[0] = f2tf32(Ps[g * KSTR + kk + t]);
            a[1] = f2tf32(Ps[(g + 8) * KSTR + kk + t]);
            a[2] = f2tf32(Ps[g * KSTR + kk + t + 4]);
            a[3] = f2tf32(Ps[(g + 8) * KSTR + kk + t + 4]);
#pragma unroll
            for (int nf = 0; nf < 8; nf++) {
                unsigned b0 = Vs[(kk + t) * VSTR + nf * 8 + g];
                unsigned b1 = Vs[(kk + t + 4) * VSTR + nf * 8 + g];
                mma_tf32(o[nf], a, b0, b1);
            }
        }
        __syncthreads();
    }

    // Write partials (unnormalized O, base-2 m, l)
    float* po = g_po + ((size_t)(b * NCHUNK + chunk) * T) * H;
#pragma unroll
    for (int nf = 0; nf < 8; nf++) {
        int col = nf * 8 + 2 * t;
        *reinterpret_cast<float2*>(po + (size_t)qra * H + col) = make_float2(o[nf][0], o[nf][1]);
        *reinterpret_cast<float2*>(po + (size_t)qrb * H + col) = make_float2(o[nf][2], o[nf][3]);
    }
    if (t == 0) {
        g_pm[((size_t)b * T + qra) * NCHUNK + chunk] = m_i[0];
        g_pl[((size_t)b * T + qra) * NCHUNK + chunk] = l_i[0];
        g_pm[((size_t)b * T + qrb) * NCHUNK + chunk] = m_i[1];
        g_pl[((size_t)b * T + qrb) * NCHUNK + chunk] = l_i[1];
    }
}

// ---------------------------------------------------------------------------
// Pass 2: combine partials. Warp per row, thread per 2 cols.
// ---------------------------------------------------------------------------
__global__ void __launch_bounds__(256) combine_kernel(float* __restrict__ out) {
    const int wid = threadIdx.x >> 5;
    const int lane = threadIdx.x & 31;
    const int row = blockIdx.x * 8 + wid;      // global row 0..16383
    const int b = row >> 11;
    const int trow = row & 2047;
    const int qt = trow >> 6;
    const int nch = qt / CHUNK_TILES + 1;
    const int col = lane * 2;

    float m2[NCHUNK], lv[NCHUNK];
    float M2 = -INFINITY;
#pragma unroll
    for (int c = 0; c < NCHUNK; c++) {
        if (c < nch) {
            m2[c] = g_pm[((size_t)b * T + trow) * NCHUNK + c];
            lv[c] = g_pl[((size_t)b * T + trow) * NCHUNK + c];
            M2 = fmaxf(M2, m2[c]);
        }
    }
    float denom = 0.f;
    float acc0 = 0.f, acc1 = 0.f;
#pragma unroll
    for (int c = 0; c < NCHUNK; c++) {
        if (c < nch) {
            float w = exp2f(m2[c] - M2);
            denom += w * lv[c];
            float2 v = *reinterpret_cast<const float2*>(
                g_po + (((size_t)(b * NCHUNK + c) * T + trow)) * H + col);
            acc0 += w * v.x;
            acc1 += w * v.y;
        }
    }
    float inv = 1.f / denom;
    *reinterpret_cast<float2*>(out + ((size_t)b * T + trow) * H + col) =
        make_float2(acc0 * inv, acc1 * inv);
}

extern "C" void kernel_launch(void* const* d_in, const int* in_sizes, int n_in,
                              void* d_out, int out_size) {
    const float* x  = (const float*)d_in[0];
    const float* Wk = (const float*)d_in[1];
    const float* Wv = (const float*)d_in[2];
    float* out = (float*)d_out;

    cudaFuncSetAttribute(attn_chunk_kernel, cudaFuncAttributeMaxDynamicSharedMemorySize, ATTN_SMEM);

    proj_kernel<<<(BATCH * T) / PBM, 256>>>(x, Wk, Wv);
    attn_chunk_kernel<<<dim3(T / BQ, NCHUNK, BATCH), 128, ATTN_SMEM>>>();
    combine_kernel<<<(BATCH * T) / 8, 256>>>(out);
}